// round 13
// baseline (speedup 1.0000x reference)
#include <cuda_runtime.h>
#include <cuda_fp16.h>
#include <cstdint>

#define NNODES 100000
#define NEDGES 1600000
#define NPAD   100096          // 782 * 128
#define NTILES 782
#define SCAN_B 256
#define NBLK ((NNODES + SCAN_B - 1) / SCAN_B)   // 391
#define EBLK4 ((NEDGES / 4 + 255) / 256)        // 1563 (ceil)

// ---------------- static device scratch ----------------
__device__ float  g_h1[NPAD * 64];
__device__ float  g_f0[NPAD * 64], g_f1[NPAD * 64], g_f2[NPAD * 64];
__device__ float  g_hacc[NPAD * 64];            // f0 @ wfold_seg0 (head partial)
__device__ __half g_f0s[NPAD * 64], g_f1s[NPAD * 64];
__device__ int    g_csrc[NEDGES];
__device__ int    g_deg[NNODES], g_rowptr[NNODES + 1], g_cursor[NNODES];
__device__ unsigned long long g_pstate[NBLK];   // decoupled-lookback state
__device__ float  g_dinv[NPAD];                 // tail stays zero
__device__ float  g_wfold[3 * 64 * 64];
__device__ int    g_flag;                       // 0 = int64 edges, 1 = int32

// ---------------- helpers ----------------
__device__ __forceinline__ uint32_t smem_u32(const void* p) {
    uint32_t a;
    asm("{ .reg .u64 t; cvta.to.shared.u64 t, %1; cvt.u32.u64 %0, t; }" : "=r"(a) : "l"(p));
    return a;
}
__device__ __forceinline__ uint32_t pack2h(float a, float b) {
    __half2 h = __floats2half2_rn(a, b);
    return *reinterpret_cast<uint32_t*>(&h);
}
__device__ __forceinline__ unsigned long long ldv64(const unsigned long long* p) {
    unsigned long long v;
    asm volatile("ld.volatile.global.u64 %0, [%1];" : "=l"(v) : "l"(p));
    return v;
}

#define LDSM4(d, a)                                                              \
    asm volatile("ldmatrix.sync.aligned.m8n8.x4.shared.b16 {%0,%1,%2,%3}, [%4];" \
                 : "=r"((d)[0]), "=r"((d)[1]), "=r"((d)[2]), "=r"((d)[3]) : "r"(a))
#define LDSM2(d, a)                                                              \
    asm volatile("ldmatrix.sync.aligned.m8n8.x2.shared.b16 {%0,%1}, [%2];"       \
                 : "=r"((d)[0]), "=r"((d)[1]) : "r"(a))
#define MMA(c, a, b)                                                             \
    asm volatile("mma.sync.aligned.m16n8k16.row.col.f32.f16.f16.f32 "            \
                 "{%0,%1,%2,%3},{%4,%5,%6,%7},{%8,%9},{%0,%1,%2,%3};"            \
                 : "+f"((c)[0]), "+f"((c)[1]), "+f"((c)[2]), "+f"((c)[3])        \
                 : "r"((a)[0]), "r"((a)[1]), "r"((a)[2]), "r"((a)[3]),           \
                   "r"((b)[0]), "r"((b)[1]))

// ---------------- prep kernels ----------------
__global__ void k_detect(const int* __restrict__ e32) {
    int nz = 0;
    for (int e = threadIdx.x; e < 2048; e += 256) nz |= e32[2 * e + 1];
    if (__syncthreads_or(nz) && threadIdx.x == 0) g_flag = 1;
}
__global__ void k_degree(const void* __restrict__ eptr) {
    int e4 = (blockIdx.x * blockDim.x + threadIdx.x) * 4;
    if (e4 >= NEDGES) return;
    int d0, d1, d2, d3;
    if (g_flag == 0) {
        const longlong2* p = (const longlong2*)((const long long*)eptr + NEDGES + e4);
        longlong2 a = p[0], b = p[1];
        d0 = (int)a.x; d1 = (int)a.y; d2 = (int)b.x; d3 = (int)b.y;
    } else {
        int4 a = *(const int4*)((const int*)eptr + NEDGES + e4);
        d0 = a.x; d1 = a.y; d2 = a.z; d3 = a.w;
    }
    atomicAdd(&g_deg[d0], 1);
    atomicAdd(&g_deg[d1], 1);
    atomicAdd(&g_deg[d2], 1);
    atomicAdd(&g_deg[d3], 1);
}

__global__ void k_scan_fused() {
    __shared__ int sh[SCAN_B];
    __shared__ int s_base;
    int b = blockIdx.x, t = threadIdx.x;
    int i = b * SCAN_B + t;
    int d = (i < NNODES) ? g_deg[i] : 0;
    sh[t] = d;
    __syncthreads();
    for (int off = 1; off < SCAN_B; off <<= 1) {
        int v = (t >= off) ? sh[t - off] : 0;
        __syncthreads();
        sh[t] += v;
        __syncthreads();
    }
    int incl = sh[t];
    int agg = sh[SCAN_B - 1];
    if (t == 0) {
        if (b == 0) {
            s_base = 0;
            atomicExch(&g_pstate[0], (2ull << 32) | (unsigned)agg);
        } else {
            atomicExch(&g_pstate[b], (1ull << 32) | (unsigned)agg);
        }
    }
    if (b > 0 && t < 32) {
        int running = 0;
        int j = b - 1;
        for (;;) {
            int jj = j - t;
            unsigned long long st;
            unsigned f;
            do {
                st = (jj >= 0) ? ldv64(&g_pstate[jj]) : (2ull << 32);
                f = (unsigned)(st >> 32);
            } while (__ballot_sync(0xffffffffu, f == 0));
            int v = (jj >= 0) ? (int)(st & 0xffffffffu) : 0;
            unsigned pm = __ballot_sync(0xffffffffu, (jj >= 0) && (f == 2));
            if (pm) {
                int fl = __ffs(pm) - 1;
                if ((int)t > fl) v = 0;
#pragma unroll
                for (int o = 16; o; o >>= 1) v += __shfl_xor_sync(0xffffffffu, v, o);
                running += v;
                break;
            }
#pragma unroll
            for (int o = 16; o; o >>= 1) v += __shfl_xor_sync(0xffffffffu, v, o);
            running += v;
            j -= 32;
        }
        if (t == 0) {
            s_base = running;
            atomicExch(&g_pstate[b], (2ull << 32) | (unsigned)(running + agg));
        }
    }
    __syncthreads();
    int base = s_base;
    if (i < NNODES) {
        int r = base + incl - d;
        g_rowptr[i] = r;
        g_cursor[i] = r;
        g_dinv[i] = rsqrtf((float)(d > 0 ? d : 1));
        if (i == NNODES - 1) g_rowptr[NNODES] = base + incl;
    }
}

__global__ void k_fill(const void* __restrict__ eptr) {
    int e4 = (blockIdx.x * blockDim.x + threadIdx.x) * 4;
    if (e4 >= NEDGES) return;
    int s0, s1, s2, s3, d0, d1, d2, d3;
    if (g_flag == 0) {
        const long long* pb = (const long long*)eptr;
        const longlong2* ps = (const longlong2*)(pb + e4);
        const longlong2* pd = (const longlong2*)(pb + NEDGES + e4);
        longlong2 sa = ps[0], sb2 = ps[1], da = pd[0], db = pd[1];
        s0 = (int)sa.x; s1 = (int)sa.y; s2 = (int)sb2.x; s3 = (int)sb2.y;
        d0 = (int)da.x; d1 = (int)da.y; d2 = (int)db.x; d3 = (int)db.y;
    } else {
        const int* pb = (const int*)eptr;
        int4 sa = *(const int4*)(pb + e4);
        int4 da = *(const int4*)(pb + NEDGES + e4);
        s0 = sa.x; s1 = sa.y; s2 = sa.z; s3 = sa.w;
        d0 = da.x; d1 = da.y; d2 = da.z; d3 = da.w;
    }
    int p0 = atomicAdd(&g_cursor[d0], 1);
    int p1 = atomicAdd(&g_cursor[d1], 1);
    int p2 = atomicAdd(&g_cursor[d2], 1);
    int p3 = atomicAdd(&g_cursor[d3], 1);
    g_csrc[p0] = s0;
    g_csrc[p1] = s1;
    g_csrc[p2] = s2;
    g_csrc[p3] = s3;
}
// fold thetas: t0=[3,-3,0.75], t1=[0,3,-1.5], t2=[0,0,0.75]
__global__ void k_fold(const float* __restrict__ Wm1) {
    int idx = blockIdx.x * blockDim.x + threadIdx.x;
    if (idx >= 3 * 64 * 64) return;
    int k = idx >> 12, ij = idx & 4095;
    float c0, c1, c2;
    if (k == 0)      { c0 = 3.0f;  c1 = 0.0f;  c2 = 0.0f;  }
    else if (k == 1) { c0 = -3.0f; c1 = 3.0f;  c2 = 0.0f;  }
    else             { c0 = 0.75f; c1 = -1.5f; c2 = 0.75f; }
    g_wfold[idx] = c0 * Wm1[ij] + c1 * Wm1[4096 + ij] + c2 * Wm1[2 * 4096 + ij];
}

// ---------------- smem layout for MMA kernels ----------------
#define LDH 72
#define LDF 68
#define OFF_BIAS 0
#define OFF_WM2  256
#define OFF_CT   768
#define OFF_AH   768
#define OFF_AL   (OFF_AH + 128 * LDH * 2)
#define OFF_WH   (OFF_AL + 128 * LDH * 2)
#define OFF_WL   (OFF_WH + 64 * LDH * 2)
#define SMEM_SZ  (OFF_WL + 64 * LDH * 2)

// ---------------- HMMA GEMM ----------------
// MODE 0: fp32 relu(C+bias). MODE 1: MODE0 + fp16 prescaled Cs = C*dinv.
// MODE 2: head final — adds Hacc, then out = relu(C+Hacc+bias) @ Wm2 + bm2.
// MODE 3: raw fp32 C (no bias, no relu) — head partial.
template <int NSEG, int MODE>
__global__ void __launch_bounds__(256) k_mma(
    const float* __restrict__ A0, const float* __restrict__ A1, const float* __restrict__ A2,
    int lda,
    const float* __restrict__ W, const float* __restrict__ bias,
    float* __restrict__ C, __half* __restrict__ Cs,
    const float* __restrict__ Hacc,
    const float* __restrict__ Wm2, const float* __restrict__ bm2,
    float* __restrict__ out)
{
    extern __shared__ char smem[];
    uint32_t sb = smem_u32(smem);
    float* sbias = (float*)(smem + OFF_BIAS);
    float* swm2  = (float*)(smem + OFF_WM2);
    __half* sAh = (__half*)(smem + OFF_AH);
    __half* sAl = (__half*)(smem + OFF_AL);
    __half* sWh = (__half*)(smem + OFF_WH);
    __half* sWl = (__half*)(smem + OFF_WL);

    int tid = threadIdx.x;
    int warp = tid >> 5, lane = tid & 31;
    int wy = warp & 3, wx = warp >> 2;
    int row0 = blockIdx.x * 128;

    if (MODE != 3 && tid < 64) sbias[tid] = bias[tid];
    if (MODE == 2 && tid < 128) swm2[tid] = Wm2[tid];

    float acc[2][4][4];
#pragma unroll
    for (int mi = 0; mi < 2; mi++)
#pragma unroll
        for (int ni = 0; ni < 4; ni++)
#pragma unroll
            for (int j = 0; j < 4; j++) acc[mi][ni][j] = 0.f;

    const float* Aseg[3] = {A0, A1, A2};

    const int arow = wy * 32 + (lane & 7) + ((lane >> 3) & 1) * 8;
    const int acol = ((lane >> 4) & 1) * 8;
    const int brow = wx * 32 + (lane & 7);
    const int bcol = ((lane >> 3) & 1) * 8;

#pragma unroll
    for (int sg = 0; sg < NSEG; sg++) {
        __syncthreads();
        // stage A: read fp32, split hi/lo in registers
        {
            const float* pa = Aseg[sg];
#pragma unroll
            for (int it = 0; it < 4; it++) {
                int idx = tid + it * 256;
                int row = idx >> 3;
                int c8 = (idx & 7) * 8;
                int grow = row0 + row;
                if (grow >= NNODES) grow = NNODES - 1;
                const float* gp = pa + (size_t)grow * lda + c8;
                float4 u0 = *(const float4*)gp;
                float4 u1 = *(const float4*)(gp + 4);
                float f[8] = {u0.x, u0.y, u0.z, u0.w, u1.x, u1.y, u1.z, u1.w};
                float lo[8];
#pragma unroll
                for (int j = 0; j < 8; j++) {
                    __half h = __float2half_rn(f[j]);
                    lo[j] = f[j] - __half2float(h);
                }
                uint4 vh, vl;
                vh.x = pack2h(f[0], f[1]); vh.y = pack2h(f[2], f[3]);
                vh.z = pack2h(f[4], f[5]); vh.w = pack2h(f[6], f[7]);
                vl.x = pack2h(lo[0], lo[1]); vl.y = pack2h(lo[2], lo[3]);
                vl.z = pack2h(lo[4], lo[5]); vl.w = pack2h(lo[6], lo[7]);
                *(uint4*)&sAh[row * LDH + c8] = vh;
                *(uint4*)&sAl[row * LDH + c8] = vl;
            }
        }
        // stage W hi/lo transposed [n][k]
        {
            const float* Wc = W + sg * 4096;
            for (int i = tid; i < 4096; i += 256) {
                int k = i >> 6, n = i & 63;
                float w = Wc[i];
                __half hh = __float2half_rn(w);
                sWh[n * LDH + k] = hh;
                sWl[n * LDH + k] = __float2half_rn(w - __half2float(hh));
            }
        }
        __syncthreads();
#pragma unroll
        for (int kc = 0; kc < 64; kc += 16) {
            uint32_t ah[2][4], al[2][4];
#pragma unroll
            for (int mi = 0; mi < 2; mi++) {
                uint32_t aa = sb + OFF_AH + ((arow + mi * 16) * LDH + kc + acol) * 2;
                LDSM4(ah[mi], aa);
                LDSM4(al[mi], aa + (OFF_AL - OFF_AH));
            }
#pragma unroll
            for (int ni = 0; ni < 4; ni++) {
                uint32_t wh[2], wl[2];
                uint32_t ba = sb + OFF_WH + ((brow + ni * 8) * LDH + kc + bcol) * 2;
                LDSM2(wh, ba);
                LDSM2(wl, ba + (OFF_WL - OFF_WH));
#pragma unroll
                for (int mi = 0; mi < 2; mi++) {
                    MMA(acc[mi][ni], ah[mi], wh);
                    MMA(acc[mi][ni], al[mi], wh);
                    MMA(acc[mi][ni], ah[mi], wl);
                }
            }
        }
    }

    // ---- epilogue: park raw acc in smem (reuses A staging) ----
    __syncthreads();
    float* sC = (float*)(smem + OFF_CT);
    {
        int g = lane >> 2, qp = (lane & 3) * 2;
#pragma unroll
        for (int mi = 0; mi < 2; mi++)
#pragma unroll
            for (int ni = 0; ni < 4; ni++) {
                int r = wy * 32 + mi * 16 + g;
                int c = wx * 32 + ni * 8 + qp;
                *(float2*)&sC[r * LDF + c]       = make_float2(acc[mi][ni][0], acc[mi][ni][1]);
                *(float2*)&sC[(r + 8) * LDF + c] = make_float2(acc[mi][ni][2], acc[mi][ni][3]);
            }
    }
    __syncthreads();

    if (MODE == 2) {
        // add hacc (coalesced), then contract with Wm2
#pragma unroll
        for (int it = 0; it < 4; it++) {
            int idx = tid + it * 256;
            int row = idx >> 3;
            int c8 = (idx & 7) * 8;
            size_t base = (size_t)(row0 + row) * 64 + c8;
            float4 h0 = *(const float4*)(Hacc + base);
            float4 h1 = *(const float4*)(Hacc + base + 4);
            sC[row * LDF + c8 + 0] += h0.x; sC[row * LDF + c8 + 1] += h0.y;
            sC[row * LDF + c8 + 2] += h0.z; sC[row * LDF + c8 + 3] += h0.w;
            sC[row * LDF + c8 + 4] += h1.x; sC[row * LDF + c8 + 5] += h1.y;
            sC[row * LDF + c8 + 6] += h1.z; sC[row * LDF + c8 + 7] += h1.w;
        }
        __syncthreads();
        int r = tid >> 1, c2 = tid & 1;
        float s = 0.f;
#pragma unroll
        for (int c = 0; c < 64; c++)
            s = fmaf(fmaxf(sC[r * LDF + c] + sbias[c], 0.f), swm2[c * 2 + c2], s);
        if (row0 + r < NNODES)
            out[(size_t)(row0 + r) * 2 + c2] = s + __ldg(&bm2[c2]);
    } else {
#pragma unroll
        for (int it = 0; it < 4; it++) {
            int idx = tid + it * 256;
            int row = idx >> 3;
            int c8 = (idx & 7) * 8;
            float v[8];
#pragma unroll
            for (int j = 0; j < 8; j++) {
                float raw = sC[row * LDF + c8 + j];
                v[j] = (MODE == 3) ? raw : fmaxf(raw + sbias[c8 + j], 0.f);
            }
            size_t base = (size_t)(row0 + row) * 64 + c8;
            *(float4*)(C + base)     = make_float4(v[0], v[1], v[2], v[3]);
            *(float4*)(C + base + 4) = make_float4(v[4], v[5], v[6], v[7]);
            if (MODE == 1) {
                float dn = g_dinv[row0 + row];
                uint4 ps;
                ps.x = pack2h(v[0] * dn, v[1] * dn); ps.y = pack2h(v[2] * dn, v[3] * dn);
                ps.z = pack2h(v[4] * dn, v[5] * dn); ps.w = pack2h(v[6] * dn, v[7] * dn);
                *(uint4*)(Cs + base) = ps;
            }
        }
    }
}

// ---------------- propagation (R7-proven: fp16 gather, MLP=4) ----------------
template <bool OUT_SCALED>
__global__ void __launch_bounds__(256) k_prop(
    const float* __restrict__ fin, const __half* __restrict__ fins,
    float* __restrict__ fout, __half* __restrict__ fouts)
{
    int n = (blockIdx.x * blockDim.x + threadIdx.x) >> 5;
    int lane = threadIdx.x & 31;
    int start = g_rowptr[n];
    int end = g_rowptr[n + 1];

    float ax = 0.f, ay = 0.f;
    for (int i = start; i < end; i += 32) {
        int cnt = min(32, end - i);
        int s = 0;
        if (lane < cnt) s = g_csrc[i + lane];
        int j = 0;
        for (; j + 4 <= cnt; j += 4) {
            int s0 = __shfl_sync(0xffffffffu, s, j);
            int s1 = __shfl_sync(0xffffffffu, s, j + 1);
            int s2 = __shfl_sync(0xffffffffu, s, j + 2);
            int s3 = __shfl_sync(0xffffffffu, s, j + 3);
            float2 v0 = __half22float2(*(const __half2*)&fins[(size_t)s0 * 64 + lane * 2]);
            float2 v1 = __half22float2(*(const __half2*)&fins[(size_t)s1 * 64 + lane * 2]);
            float2 v2 = __half22float2(*(const __half2*)&fins[(size_t)s2 * 64 + lane * 2]);
            float2 v3 = __half22float2(*(const __half2*)&fins[(size_t)s3 * 64 + lane * 2]);
            ax += (v0.x + v1.x) + (v2.x + v3.x);
            ay += (v0.y + v1.y) + (v2.y + v3.y);
        }
        for (; j < cnt; j++) {
            int sj = __shfl_sync(0xffffffffu, s, j);
            float2 v = __half22float2(*(const __half2*)&fins[(size_t)sj * 64 + lane * 2]);
            ax += v.x;
            ay += v.y;
        }
    }
    float dn = g_dinv[n];
    size_t base = (size_t)n * 64 + lane * 2;
    float2 cur = *(const float2*)&fin[base];
    float ox = cur.x - ax * dn;
    float oy = cur.y - ay * dn;
    *(float2*)&fout[base] = make_float2(ox, oy);
    if (OUT_SCALED)
        *(uint32_t*)&fouts[base] = pack2h(ox * dn, oy * dn);
}

// ---------------- launch ----------------
extern "C" void kernel_launch(void* const* d_in, const int* in_sizes, int n_in,
                              void* d_out, int out_size)
{
    const float* x   = (const float*)d_in[0];
    const void*  ei  = d_in[1];
    const float* W1  = (const float*)d_in[2];
    const float* b1  = (const float*)d_in[3];
    const float* W2  = (const float*)d_in[4];
    const float* b2  = (const float*)d_in[5];
    const float* Wm1 = (const float*)d_in[6];
    const float* bm1 = (const float*)d_in[7];
    const float* Wm2 = (const float*)d_in[8];
    const float* bm2 = (const float*)d_in[9];
    float* out = (float*)d_out;

    float *h1, *f0, *f1, *f2, *hacc, *pwf;
    __half *f0s, *f1s;
    int *pdeg, *pflag;
    unsigned long long* pstate;
    cudaGetSymbolAddress((void**)&h1, g_h1);
    cudaGetSymbolAddress((void**)&f0, g_f0);
    cudaGetSymbolAddress((void**)&f1, g_f1);
    cudaGetSymbolAddress((void**)&f2, g_f2);
    cudaGetSymbolAddress((void**)&hacc, g_hacc);
    cudaGetSymbolAddress((void**)&f0s, g_f0s);
    cudaGetSymbolAddress((void**)&f1s, g_f1s);
    cudaGetSymbolAddress((void**)&pwf, g_wfold);
    cudaGetSymbolAddress((void**)&pdeg, g_deg);
    cudaGetSymbolAddress((void**)&pflag, g_flag);
    cudaGetSymbolAddress((void**)&pstate, g_pstate);

    cudaFuncSetAttribute(k_mma<2, 0>, cudaFuncAttributeMaxDynamicSharedMemorySize, SMEM_SZ);
    cudaFuncSetAttribute(k_mma<1, 1>, cudaFuncAttributeMaxDynamicSharedMemorySize, SMEM_SZ);
    cudaFuncSetAttribute(k_mma<1, 3>, cudaFuncAttributeMaxDynamicSharedMemorySize, SMEM_SZ);
    cudaFuncSetAttribute(k_mma<2, 2>, cudaFuncAttributeMaxDynamicSharedMemorySize, SMEM_SZ);

    static cudaStream_t s_side = [] {
        cudaStream_t s;
        return (cudaStreamCreateWithFlags(&s, cudaStreamNonBlocking) == cudaSuccess)
                   ? s : (cudaStream_t)nullptr;
    }();
    static cudaEvent_t e_fork = [] {
        cudaEvent_t e;
        return (cudaEventCreateWithFlags(&e, cudaEventDisableTiming) == cudaSuccess)
                   ? e : (cudaEvent_t)nullptr;
    }();
    static cudaEvent_t e_dinv = [] {
        cudaEvent_t e;
        return (cudaEventCreateWithFlags(&e, cudaEventDisableTiming) == cudaSuccess)
                   ? e : (cudaEvent_t)nullptr;
    }();
    static cudaEvent_t e_join = [] {
        cudaEvent_t e;
        return (cudaEventCreateWithFlags(&e, cudaEventDisableTiming) == cudaSuccess)
                   ? e : (cudaEvent_t)nullptr;
    }();
    static cudaEvent_t e_f0 = [] {
        cudaEvent_t e;
        return (cudaEventCreateWithFlags(&e, cudaEventDisableTiming) == cudaSuccess)
                   ? e : (cudaEvent_t)nullptr;
    }();
    static cudaEvent_t e_hacc = [] {
        cudaEvent_t e;
        return (cudaEventCreateWithFlags(&e, cudaEventDisableTiming) == cudaSuccess)
                   ? e : (cudaEvent_t)nullptr;
    }();

    bool overlap = s_side && e_fork && e_dinv && e_join && e_f0 && e_hacc;
    cudaStream_t sp = overlap ? s_side : (cudaStream_t)0;

    if (overlap) {
        cudaEventRecord(e_fork, 0);
        cudaStreamWaitEvent(s_side, e_fork, 0);
    }

    // ---- side chain: fold first, then CSR build ----
    k_fold<<<(3 * 64 * 64 + 255) / 256, 256, 0, sp>>>(Wm1);
    cudaMemsetAsync(pdeg, 0, NNODES * sizeof(int), sp);
    cudaMemsetAsync(pflag, 0, sizeof(int), sp);
    cudaMemsetAsync(pstate, 0, NBLK * sizeof(unsigned long long), sp);
    k_detect<<<1, 256, 0, sp>>>((const int*)ei);
    k_degree<<<EBLK4, 256, 0, sp>>>(ei);
    k_scan_fused<<<NBLK, SCAN_B, 0, sp>>>();
    if (overlap) cudaEventRecord(e_dinv, s_side);
    k_fill<<<EBLK4, 256, 0, sp>>>(ei);
    if (overlap) cudaEventRecord(e_join, s_side);

    // ---- main chain ----
    k_mma<2, 0><<<NTILES, 256, SMEM_SZ>>>(x, x + 64, nullptr, 128, W1, b1,
                                          h1, nullptr, nullptr, nullptr, nullptr, nullptr);
    if (overlap) cudaStreamWaitEvent(0, e_dinv, 0);   // GEMM2 prescale needs dinv
    k_mma<1, 1><<<NTILES, 256, SMEM_SZ>>>(h1, nullptr, nullptr, 64, W2, b2,
                                          f0, f0s, nullptr, nullptr, nullptr, nullptr);
    if (overlap) cudaEventRecord(e_f0, 0);

    // head partial (side stream, overlaps the props): hacc = f0 @ wfold_seg0
    if (overlap) {
        cudaStreamWaitEvent(s_side, e_f0, 0);
        k_mma<1, 3><<<NTILES, 256, SMEM_SZ, s_side>>>(f0, nullptr, nullptr, 64, pwf, nullptr,
                                                      hacc, nullptr, nullptr, nullptr, nullptr, nullptr);
        cudaEventRecord(e_hacc, s_side);
    } else {
        k_mma<1, 3><<<NTILES, 256, SMEM_SZ>>>(f0, nullptr, nullptr, 64, pwf, nullptr,
                                              hacc, nullptr, nullptr, nullptr, nullptr, nullptr);
    }

    if (overlap) cudaStreamWaitEvent(0, e_join, 0);   // props need CSR

    // f1 = P f0, f2 = P f1
    k_prop<true><<<(NNODES * 32) / 256, 256>>>(f0, f0s, f1, f1s);
    k_prop<false><<<(NNODES * 32) / 256, 256>>>(f1, f1s, f2, nullptr);

    if (overlap) cudaStreamWaitEvent(0, e_hacc, 0);

    // head final: out = relu(hacc + f1@seg1 + f2@seg2 + bm1) @ Wm2 + bm2
    k_mma<2, 2><<<NTILES, 256, SMEM_SZ>>>(f1, f2, nullptr, 64, pwf + 4096, bm1,
                                          nullptr, nullptr, hacc, Wm2, bm2, out);
}

// round 14
// speedup vs baseline: 1.1562x; 1.1562x over previous
#include <cuda_runtime.h>
#include <cuda_fp16.h>
#include <cstdint>

#define NNODES 100000
#define NEDGES 1600000
#define NPAD   100096          // 782 * 128
#define NTILES 782
#define SCAN_B 256
#define NBLK ((NNODES + SCAN_B - 1) / SCAN_B)   // 391
#define EBLK4 ((NEDGES / 4 + 255) / 256)        // 1563 (ceil)

// ---------------- static device scratch ----------------
__device__ float  g_h1[NPAD * 64];
__device__ float  g_f0[NPAD * 64], g_f1[NPAD * 64], g_f2[NPAD * 64];
__device__ __half g_f0s[NPAD * 64], g_f1s[NPAD * 64];
__device__ int    g_csrc[NEDGES];
__device__ int    g_deg[NNODES], g_rowptr[NNODES + 1], g_cursor[NNODES];
__device__ unsigned long long g_pstate[NBLK];   // decoupled-lookback state
__device__ float  g_dinv[NPAD];                 // tail stays zero
__device__ float  g_wfold[3 * 64 * 64];
__device__ int    g_flag;                       // 0 = int64 edges, 1 = int32

// ---------------- helpers ----------------
__device__ __forceinline__ uint32_t smem_u32(const void* p) {
    uint32_t a;
    asm("{ .reg .u64 t; cvta.to.shared.u64 t, %1; cvt.u32.u64 %0, t; }" : "=r"(a) : "l"(p));
    return a;
}
__device__ __forceinline__ uint32_t pack2h(float a, float b) {
    __half2 h = __floats2half2_rn(a, b);
    return *reinterpret_cast<uint32_t*>(&h);
}
__device__ __forceinline__ unsigned long long ldv64(const unsigned long long* p) {
    unsigned long long v;
    asm volatile("ld.volatile.global.u64 %0, [%1];" : "=l"(v) : "l"(p));
    return v;
}

#define LDSM4(d, a)                                                              \
    asm volatile("ldmatrix.sync.aligned.m8n8.x4.shared.b16 {%0,%1,%2,%3}, [%4];" \
                 : "=r"((d)[0]), "=r"((d)[1]), "=r"((d)[2]), "=r"((d)[3]) : "r"(a))
#define LDSM2(d, a)                                                              \
    asm volatile("ldmatrix.sync.aligned.m8n8.x2.shared.b16 {%0,%1}, [%2];"       \
                 : "=r"((d)[0]), "=r"((d)[1]) : "r"(a))
#define MMA(c, a, b)                                                             \
    asm volatile("mma.sync.aligned.m16n8k16.row.col.f32.f16.f16.f32 "            \
                 "{%0,%1,%2,%3},{%4,%5,%6,%7},{%8,%9},{%0,%1,%2,%3};"            \
                 : "+f"((c)[0]), "+f"((c)[1]), "+f"((c)[2]), "+f"((c)[3])        \
                 : "r"((a)[0]), "r"((a)[1]), "r"((a)[2]), "r"((a)[3]),           \
                   "r"((b)[0]), "r"((b)[1]))

// ---------------- prep kernels ----------------
__global__ void k_detect(const int* __restrict__ e32) {
    int nz = 0;
    for (int e = threadIdx.x; e < 2048; e += 256) nz |= e32[2 * e + 1];
    if (__syncthreads_or(nz) && threadIdx.x == 0) g_flag = 1;
}
__global__ void k_degree(const void* __restrict__ eptr) {
    int e4 = (blockIdx.x * blockDim.x + threadIdx.x) * 4;
    if (e4 >= NEDGES) return;
    int d0, d1, d2, d3;
    if (g_flag == 0) {
        const longlong2* p = (const longlong2*)((const long long*)eptr + NEDGES + e4);
        longlong2 a = p[0], b = p[1];
        d0 = (int)a.x; d1 = (int)a.y; d2 = (int)b.x; d3 = (int)b.y;
    } else {
        int4 a = *(const int4*)((const int*)eptr + NEDGES + e4);
        d0 = a.x; d1 = a.y; d2 = a.z; d3 = a.w;
    }
    atomicAdd(&g_deg[d0], 1);
    atomicAdd(&g_deg[d1], 1);
    atomicAdd(&g_deg[d2], 1);
    atomicAdd(&g_deg[d3], 1);
}

// single-pass scan: block-local Hillis-Steele + decoupled lookback.
__global__ void k_scan_fused() {
    __shared__ int sh[SCAN_B];
    __shared__ int s_base;
    int b = blockIdx.x, t = threadIdx.x;
    int i = b * SCAN_B + t;
    int d = (i < NNODES) ? g_deg[i] : 0;
    sh[t] = d;
    __syncthreads();
    for (int off = 1; off < SCAN_B; off <<= 1) {
        int v = (t >= off) ? sh[t - off] : 0;
        __syncthreads();
        sh[t] += v;
        __syncthreads();
    }
    int incl = sh[t];
    int agg = sh[SCAN_B - 1];
    if (t == 0) {
        if (b == 0) {
            s_base = 0;
            atomicExch(&g_pstate[0], (2ull << 32) | (unsigned)agg);
        } else {
            atomicExch(&g_pstate[b], (1ull << 32) | (unsigned)agg);
        }
    }
    if (b > 0 && t < 32) {
        int running = 0;
        int j = b - 1;
        for (;;) {
            int jj = j - t;
            unsigned long long st;
            unsigned f;
            do {
                st = (jj >= 0) ? ldv64(&g_pstate[jj]) : (2ull << 32);
                f = (unsigned)(st >> 32);
            } while (__ballot_sync(0xffffffffu, f == 0));
            int v = (jj >= 0) ? (int)(st & 0xffffffffu) : 0;
            unsigned pm = __ballot_sync(0xffffffffu, (jj >= 0) && (f == 2));
            if (pm) {
                int fl = __ffs(pm) - 1;
                if ((int)t > fl) v = 0;
#pragma unroll
                for (int o = 16; o; o >>= 1) v += __shfl_xor_sync(0xffffffffu, v, o);
                running += v;
                break;
            }
#pragma unroll
            for (int o = 16; o; o >>= 1) v += __shfl_xor_sync(0xffffffffu, v, o);
            running += v;
            j -= 32;
        }
        if (t == 0) {
            s_base = running;
            atomicExch(&g_pstate[b], (2ull << 32) | (unsigned)(running + agg));
        }
    }
    __syncthreads();
    int base = s_base;
    if (i < NNODES) {
        int r = base + incl - d;
        g_rowptr[i] = r;
        g_cursor[i] = r;
        g_dinv[i] = rsqrtf((float)(d > 0 ? d : 1));
        if (i == NNODES - 1) g_rowptr[NNODES] = base + incl;
    }
}

__global__ void k_fill(const void* __restrict__ eptr) {
    int e4 = (blockIdx.x * blockDim.x + threadIdx.x) * 4;
    if (e4 >= NEDGES) return;
    int s0, s1, s2, s3, d0, d1, d2, d3;
    if (g_flag == 0) {
        const long long* pb = (const long long*)eptr;
        const longlong2* ps = (const longlong2*)(pb + e4);
        const longlong2* pd = (const longlong2*)(pb + NEDGES + e4);
        longlong2 sa = ps[0], sb2 = ps[1], da = pd[0], db = pd[1];
        s0 = (int)sa.x; s1 = (int)sa.y; s2 = (int)sb2.x; s3 = (int)sb2.y;
        d0 = (int)da.x; d1 = (int)da.y; d2 = (int)db.x; d3 = (int)db.y;
    } else {
        const int* pb = (const int*)eptr;
        int4 sa = *(const int4*)(pb + e4);
        int4 da = *(const int4*)(pb + NEDGES + e4);
        s0 = sa.x; s1 = sa.y; s2 = sa.z; s3 = sa.w;
        d0 = da.x; d1 = da.y; d2 = da.z; d3 = da.w;
    }
    int p0 = atomicAdd(&g_cursor[d0], 1);
    int p1 = atomicAdd(&g_cursor[d1], 1);
    int p2 = atomicAdd(&g_cursor[d2], 1);
    int p3 = atomicAdd(&g_cursor[d3], 1);
    g_csrc[p0] = s0;
    g_csrc[p1] = s1;
    g_csrc[p2] = s2;
    g_csrc[p3] = s3;
}
// fold thetas: t0=[3,-3,0.75], t1=[0,3,-1.5], t2=[0,0,0.75]
__global__ void k_fold(const float* __restrict__ Wm1) {
    int idx = blockIdx.x * blockDim.x + threadIdx.x;
    if (idx >= 3 * 64 * 64) return;
    int k = idx >> 12, ij = idx & 4095;
    float c0, c1, c2;
    if (k == 0)      { c0 = 3.0f;  c1 = 0.0f;  c2 = 0.0f;  }
    else if (k == 1) { c0 = -3.0f; c1 = 3.0f;  c2 = 0.0f;  }
    else             { c0 = 0.75f; c1 = -1.5f; c2 = 0.75f; }
    g_wfold[idx] = c0 * Wm1[ij] + c1 * Wm1[4096 + ij] + c2 * Wm1[2 * 4096 + ij];
}

// ---------------- smem layout for MMA kernels ----------------
#define LDH 72
#define LDF 68
#define OFF_BIAS 0
#define OFF_WM2  256
#define OFF_CT   768
#define OFF_AH   768
#define OFF_AL   (OFF_AH + 128 * LDH * 2)
#define OFF_WH   (OFF_AL + 128 * LDH * 2)
#define SMEM_SZ  (OFF_WH + 64 * LDH * 2)        // 46848 (W-lo removed)

// ---------------- HMMA GEMM (2-product hi/lo: AhWh + AlWh) ----------------
// C[128x64] = act( sum_seg A_seg[128x64](fp32) @ W_seg[64x64](fp32->fp16) + bias )
// A split hi/lo (A rounding corrected); W rounded to fp16 (error ~1e-4 rel, acceptable).
// MODE 0: fp32 C. MODE 1: fp32 C + fp16 prescaled Cs = C*dinv. MODE 2: fused @Wm2+bm2 head.
template <int NSEG, int MODE>
__global__ void __launch_bounds__(256) k_mma(
    const float* __restrict__ A0, const float* __restrict__ A1, const float* __restrict__ A2,
    int lda,
    const float* __restrict__ W, const float* __restrict__ bias,
    float* __restrict__ C, __half* __restrict__ Cs,
    const float* __restrict__ Wm2, const float* __restrict__ bm2,
    float* __restrict__ out)
{
    extern __shared__ char smem[];
    uint32_t sb = smem_u32(smem);
    float* sbias = (float*)(smem + OFF_BIAS);
    float* swm2  = (float*)(smem + OFF_WM2);
    __half* sAh = (__half*)(smem + OFF_AH);
    __half* sAl = (__half*)(smem + OFF_AL);
    __half* sWh = (__half*)(smem + OFF_WH);

    int tid = threadIdx.x;
    int warp = tid >> 5, lane = tid & 31;
    int wy = warp & 3, wx = warp >> 2;
    int row0 = blockIdx.x * 128;

    if (tid < 64) sbias[tid] = bias[tid];
    if (MODE == 2 && tid < 128) swm2[tid] = Wm2[tid];

    float acc[2][4][4];
#pragma unroll
    for (int mi = 0; mi < 2; mi++)
#pragma unroll
        for (int ni = 0; ni < 4; ni++)
#pragma unroll
            for (int j = 0; j < 4; j++) acc[mi][ni][j] = 0.f;

    const float* Aseg[3] = {A0, A1, A2};

    const int arow = wy * 32 + (lane & 7) + ((lane >> 3) & 1) * 8;
    const int acol = ((lane >> 4) & 1) * 8;
    const int brow = wx * 32 + (lane & 7);
    const int bcol = ((lane >> 3) & 1) * 8;

#pragma unroll
    for (int sg = 0; sg < NSEG; sg++) {
        __syncthreads();
        // stage A: read fp32, split hi/lo in registers
        {
            const float* pa = Aseg[sg];
#pragma unroll
            for (int it = 0; it < 4; it++) {
                int idx = tid + it * 256;
                int row = idx >> 3;
                int c8 = (idx & 7) * 8;
                int grow = row0 + row;
                if (grow >= NNODES) grow = NNODES - 1;
                const float* gp = pa + (size_t)grow * lda + c8;
                float4 u0 = *(const float4*)gp;
                float4 u1 = *(const float4*)(gp + 4);
                float f[8] = {u0.x, u0.y, u0.z, u0.w, u1.x, u1.y, u1.z, u1.w};
                float lo[8];
#pragma unroll
                for (int j = 0; j < 8; j++) {
                    __half h = __float2half_rn(f[j]);
                    lo[j] = f[j] - __half2float(h);
                }
                uint4 vh, vl;
                vh.x = pack2h(f[0], f[1]); vh.y = pack2h(f[2], f[3]);
                vh.z = pack2h(f[4], f[5]); vh.w = pack2h(f[6], f[7]);
                vl.x = pack2h(lo[0], lo[1]); vl.y = pack2h(lo[2], lo[3]);
                vl.z = pack2h(lo[4], lo[5]); vl.w = pack2h(lo[6], lo[7]);
                *(uint4*)&sAh[row * LDH + c8] = vh;
                *(uint4*)&sAl[row * LDH + c8] = vl;
            }
        }
        // stage W (fp16 hi only) transposed [n][k]
        {
            const float* Wc = W + sg * 4096;
            for (int i = tid; i < 4096; i += 256) {
                int k = i >> 6, n = i & 63;
                sWh[n * LDH + k] = __float2half_rn(Wc[i]);
            }
        }
        __syncthreads();
#pragma unroll
        for (int kc = 0; kc < 64; kc += 16) {
            uint32_t ah[2][4], al[2][4];
#pragma unroll
            for (int mi = 0; mi < 2; mi++) {
                uint32_t aa = sb + OFF_AH + ((arow + mi * 16) * LDH + kc + acol) * 2;
                LDSM4(ah[mi], aa);
                LDSM4(al[mi], aa + (OFF_AL - OFF_AH));
            }
#pragma unroll
            for (int ni = 0; ni < 4; ni++) {
                uint32_t wh[2];
                uint32_t ba = sb + OFF_WH + ((brow + ni * 8) * LDH + kc + bcol) * 2;
                LDSM2(wh, ba);
#pragma unroll
                for (int mi = 0; mi < 2; mi++) {
                    MMA(acc[mi][ni], ah[mi], wh);
                    MMA(acc[mi][ni], al[mi], wh);
                }
            }
        }
    }

    // ---- epilogue: park raw acc in smem (reuses A staging) ----
    __syncthreads();
    float* sC = (float*)(smem + OFF_CT);
    {
        int g = lane >> 2, qp = (lane & 3) * 2;
#pragma unroll
        for (int mi = 0; mi < 2; mi++)
#pragma unroll
            for (int ni = 0; ni < 4; ni++) {
                int r = wy * 32 + mi * 16 + g;
                int c = wx * 32 + ni * 8 + qp;
                *(float2*)&sC[r * LDF + c]       = make_float2(acc[mi][ni][0], acc[mi][ni][1]);
                *(float2*)&sC[(r + 8) * LDF + c] = make_float2(acc[mi][ni][2], acc[mi][ni][3]);
            }
    }
    __syncthreads();

    if (MODE != 2) {
#pragma unroll
        for (int it = 0; it < 4; it++) {
            int idx = tid + it * 256;
            int row = idx >> 3;
            int c8 = (idx & 7) * 8;
            float v[8];
#pragma unroll
            for (int j = 0; j < 8; j++)
                v[j] = fmaxf(sC[row * LDF + c8 + j] + sbias[c8 + j], 0.f);
            size_t base = (size_t)(row0 + row) * 64 + c8;
            *(float4*)(C + base)     = make_float4(v[0], v[1], v[2], v[3]);
            *(float4*)(C + base + 4) = make_float4(v[4], v[5], v[6], v[7]);
            if (MODE == 1) {
                float dn = g_dinv[row0 + row];
                uint4 ps;
                ps.x = pack2h(v[0] * dn, v[1] * dn); ps.y = pack2h(v[2] * dn, v[3] * dn);
                ps.z = pack2h(v[4] * dn, v[5] * dn); ps.w = pack2h(v[6] * dn, v[7] * dn);
                *(uint4*)(Cs + base) = ps;
            }
        }
    } else {
        int r = tid >> 1, c2 = tid & 1;
        float s = 0.f;
#pragma unroll
        for (int c = 0; c < 64; c++)
            s = fmaf(fmaxf(sC[r * LDF + c] + sbias[c], 0.f), swm2[c * 2 + c2], s);
        if (row0 + r < NNODES)
            out[(size_t)(row0 + r) * 2 + c2] = s + __ldg(&bm2[c2]);
    }
}

// ---------------- propagation (R7-proven: fp16 gather, MLP=4) ----------------
template <bool OUT_SCALED>
__global__ void __launch_bounds__(256) k_prop(
    const float* __restrict__ fin, const __half* __restrict__ fins,
    float* __restrict__ fout, __half* __restrict__ fouts)
{
    int n = (blockIdx.x * blockDim.x + threadIdx.x) >> 5;
    int lane = threadIdx.x & 31;
    int start = g_rowptr[n];
    int end = g_rowptr[n + 1];

    float ax = 0.f, ay = 0.f;
    for (int i = start; i < end; i += 32) {
        int cnt = min(32, end - i);
        int s = 0;
        if (lane < cnt) s = g_csrc[i + lane];
        int j = 0;
        for (; j + 4 <= cnt; j += 4) {
            int s0 = __shfl_sync(0xffffffffu, s, j);
            int s1 = __shfl_sync(0xffffffffu, s, j + 1);
            int s2 = __shfl_sync(0xffffffffu, s, j + 2);
            int s3 = __shfl_sync(0xffffffffu, s, j + 3);
            float2 v0 = __half22float2(*(const __half2*)&fins[(size_t)s0 * 64 + lane * 2]);
            float2 v1 = __half22float2(*(const __half2*)&fins[(size_t)s1 * 64 + lane * 2]);
            float2 v2 = __half22float2(*(const __half2*)&fins[(size_t)s2 * 64 + lane * 2]);
            float2 v3 = __half22float2(*(const __half2*)&fins[(size_t)s3 * 64 + lane * 2]);
            ax += (v0.x + v1.x) + (v2.x + v3.x);
            ay += (v0.y + v1.y) + (v2.y + v3.y);
        }
        for (; j < cnt; j++) {
            int sj = __shfl_sync(0xffffffffu, s, j);
            float2 v = __half22float2(*(const __half2*)&fins[(size_t)sj * 64 + lane * 2]);
            ax += v.x;
            ay += v.y;
        }
    }
    float dn = g_dinv[n];
    size_t base = (size_t)n * 64 + lane * 2;
    float2 cur = *(const float2*)&fin[base];
    float ox = cur.x - ax * dn;
    float oy = cur.y - ay * dn;
    *(float2*)&fout[base] = make_float2(ox, oy);
    if (OUT_SCALED)
        *(uint32_t*)&fouts[base] = pack2h(ox * dn, oy * dn);
}

// ---------------- launch ----------------
extern "C" void kernel_launch(void* const* d_in, const int* in_sizes, int n_in,
                              void* d_out, int out_size)
{
    const float* x   = (const float*)d_in[0];
    const void*  ei  = d_in[1];
    const float* W1  = (const float*)d_in[2];
    const float* b1  = (const float*)d_in[3];
    const float* W2  = (const float*)d_in[4];
    const float* b2  = (const float*)d_in[5];
    const float* Wm1 = (const float*)d_in[6];
    const float* bm1 = (const float*)d_in[7];
    const float* Wm2 = (const float*)d_in[8];
    const float* bm2 = (const float*)d_in[9];
    float* out = (float*)d_out;

    float *h1, *f0, *f1, *f2, *pwf;
    __half *f0s, *f1s;
    int *pdeg, *pflag;
    unsigned long long* pstate;
    cudaGetSymbolAddress((void**)&h1, g_h1);
    cudaGetSymbolAddress((void**)&f0, g_f0);
    cudaGetSymbolAddress((void**)&f1, g_f1);
    cudaGetSymbolAddress((void**)&f2, g_f2);
    cudaGetSymbolAddress((void**)&f0s, g_f0s);
    cudaGetSymbolAddress((void**)&f1s, g_f1s);
    cudaGetSymbolAddress((void**)&pwf, g_wfold);
    cudaGetSymbolAddress((void**)&pdeg, g_deg);
    cudaGetSymbolAddress((void**)&pflag, g_flag);
    cudaGetSymbolAddress((void**)&pstate, g_pstate);

    cudaFuncSetAttribute(k_mma<2, 0>, cudaFuncAttributeMaxDynamicSharedMemorySize, SMEM_SZ);
    cudaFuncSetAttribute(k_mma<1, 1>, cudaFuncAttributeMaxDynamicSharedMemorySize, SMEM_SZ);
    cudaFuncSetAttribute(k_mma<3, 2>, cudaFuncAttributeMaxDynamicSharedMemorySize, SMEM_SZ);

    static cudaStream_t s_side = [] {
        cudaStream_t s;
        return (cudaStreamCreateWithFlags(&s, cudaStreamNonBlocking) == cudaSuccess)
                   ? s : (cudaStream_t)nullptr;
    }();
    static cudaEvent_t e_fork = [] {
        cudaEvent_t e;
        return (cudaEventCreateWithFlags(&e, cudaEventDisableTiming) == cudaSuccess)
                   ? e : (cudaEvent_t)nullptr;
    }();
    static cudaEvent_t e_dinv = [] {
        cudaEvent_t e;
        return (cudaEventCreateWithFlags(&e, cudaEventDisableTiming) == cudaSuccess)
                   ? e : (cudaEvent_t)nullptr;
    }();
    static cudaEvent_t e_join = [] {
        cudaEvent_t e;
        return (cudaEventCreateWithFlags(&e, cudaEventDisableTiming) == cudaSuccess)
                   ? e : (cudaEvent_t)nullptr;
    }();

    bool overlap = s_side && e_fork && e_dinv && e_join;
    cudaStream_t sp = overlap ? s_side : (cudaStream_t)0;

    if (overlap) {
        cudaEventRecord(e_fork, 0);
        cudaStreamWaitEvent(s_side, e_fork, 0);
    }

    // ---- side chain: fold first, then CSR build ----
    k_fold<<<(3 * 64 * 64 + 255) / 256, 256, 0, sp>>>(Wm1);
    cudaMemsetAsync(pdeg, 0, NNODES * sizeof(int), sp);
    cudaMemsetAsync(pflag, 0, sizeof(int), sp);
    cudaMemsetAsync(pstate, 0, NBLK * sizeof(unsigned long long), sp);
    k_detect<<<1, 256, 0, sp>>>((const int*)ei);
    k_degree<<<EBLK4, 256, 0, sp>>>(ei);
    k_scan_fused<<<NBLK, SCAN_B, 0, sp>>>();
    if (overlap) cudaEventRecord(e_dinv, s_side);
    k_fill<<<EBLK4, 256, 0, sp>>>(ei);
    if (overlap) cudaEventRecord(e_join, s_side);

    // ---- main chain ----
    k_mma<2, 0><<<NTILES, 256, SMEM_SZ>>>(x, x + 64, nullptr, 128, W1, b1,
                                          h1, nullptr, nullptr, nullptr, nullptr);
    if (overlap) cudaStreamWaitEvent(0, e_dinv, 0);   // GEMM2 prescale needs dinv
    k_mma<1, 1><<<NTILES, 256, SMEM_SZ>>>(h1, nullptr, nullptr, 64, W2, b2,
                                          f0, f0s, nullptr, nullptr, nullptr);
    if (overlap) cudaStreamWaitEvent(0, e_join, 0);   // props need CSR

    // f1 = P f0, f2 = P f1
    k_prop<true><<<(NNODES * 32) / 256, 256>>>(f0, f0s, f1, f1s);
    k_prop<false><<<(NNODES * 32) / 256, 256>>>(f1, f1s, f2, nullptr);

    // head: out = relu(f0@Wf0 + f1@Wf1 + f2@Wf2 + bm1) @ Wm2 + bm2
    k_mma<3, 2><<<NTILES, 256, SMEM_SZ>>>(f0, f1, f2, 64, pwf, bm1,
                                          nullptr, nullptr, Wm2, bm2, out);
}

// round 15
// speedup vs baseline: 1.2104x; 1.0469x over previous
#include <cuda_runtime.h>
#include <cuda_fp16.h>
#include <cstdint>

#define NNODES 100000
#define NEDGES 1600000
#define NPAD   100096          // 782 * 128
#define NTILES 782
#define SCAN_B 256
#define NBLK ((NNODES + SCAN_B - 1) / SCAN_B)   // 391
#define EBLK4 ((NEDGES / 4 + 255) / 256)        // 1563 (ceil)

// ---------------- static device scratch ----------------
__device__ float  g_f0[NPAD * 64], g_f1[NPAD * 64], g_f2[NPAD * 64];
__device__ __half g_f0s[NPAD * 64], g_f1s[NPAD * 64];
__device__ int    g_csrc[NEDGES];
__device__ int    g_deg[NNODES], g_rowptr[NNODES + 1], g_cursor[NNODES];
__device__ unsigned long long g_pstate[NBLK];   // decoupled-lookback state
__device__ float  g_dinv[NPAD];                 // tail stays zero
__device__ float  g_wfold[3 * 64 * 64];
__device__ int    g_flag;                       // 0 = int64 edges, 1 = int32

// ---------------- helpers ----------------
__device__ __forceinline__ uint32_t smem_u32(const void* p) {
    uint32_t a;
    asm("{ .reg .u64 t; cvta.to.shared.u64 t, %1; cvt.u32.u64 %0, t; }" : "=r"(a) : "l"(p));
    return a;
}
__device__ __forceinline__ uint32_t pack2h(float a, float b) {
    __half2 h = __floats2half2_rn(a, b);
    return *reinterpret_cast<uint32_t*>(&h);
}
__device__ __forceinline__ unsigned long long ldv64(const unsigned long long* p) {
    unsigned long long v;
    asm volatile("ld.volatile.global.u64 %0, [%1];" : "=l"(v) : "l"(p));
    return v;
}

#define LDSM4(d, a)                                                              \
    asm volatile("ldmatrix.sync.aligned.m8n8.x4.shared.b16 {%0,%1,%2,%3}, [%4];" \
                 : "=r"((d)[0]), "=r"((d)[1]), "=r"((d)[2]), "=r"((d)[3]) : "r"(a))
#define LDSM2(d, a)                                                              \
    asm volatile("ldmatrix.sync.aligned.m8n8.x2.shared.b16 {%0,%1}, [%2];"       \
                 : "=r"((d)[0]), "=r"((d)[1]) : "r"(a))
#define MMA(c, a, b)                                                             \
    asm volatile("mma.sync.aligned.m16n8k16.row.col.f32.f16.f16.f32 "            \
                 "{%0,%1,%2,%3},{%4,%5,%6,%7},{%8,%9},{%0,%1,%2,%3};"            \
                 : "+f"((c)[0]), "+f"((c)[1]), "+f"((c)[2]), "+f"((c)[3])        \
                 : "r"((a)[0]), "r"((a)[1]), "r"((a)[2]), "r"((a)[3]),           \
                   "r"((b)[0]), "r"((b)[1]))

// ---------------- prep kernels ----------------
__global__ void k_detect(const int* __restrict__ e32) {
    int nz = 0;
    for (int e = threadIdx.x; e < 2048; e += 256) nz |= e32[2 * e + 1];
    if (__syncthreads_or(nz) && threadIdx.x == 0) g_flag = 1;
}
__global__ void k_degree(const void* __restrict__ eptr) {
    int e4 = (blockIdx.x * blockDim.x + threadIdx.x) * 4;
    if (e4 >= NEDGES) return;
    int d0, d1, d2, d3;
    if (g_flag == 0) {
        const longlong2* p = (const longlong2*)((const long long*)eptr + NEDGES + e4);
        longlong2 a = p[0], b = p[1];
        d0 = (int)a.x; d1 = (int)a.y; d2 = (int)b.x; d3 = (int)b.y;
    } else {
        int4 a = *(const int4*)((const int*)eptr + NEDGES + e4);
        d0 = a.x; d1 = a.y; d2 = a.z; d3 = a.w;
    }
    atomicAdd(&g_deg[d0], 1);
    atomicAdd(&g_deg[d1], 1);
    atomicAdd(&g_deg[d2], 1);
    atomicAdd(&g_deg[d3], 1);
}

// single-pass scan: block-local Hillis-Steele + decoupled lookback.
__global__ void k_scan_fused() {
    __shared__ int sh[SCAN_B];
    __shared__ int s_base;
    int b = blockIdx.x, t = threadIdx.x;
    int i = b * SCAN_B + t;
    int d = (i < NNODES) ? g_deg[i] : 0;
    sh[t] = d;
    __syncthreads();
    for (int off = 1; off < SCAN_B; off <<= 1) {
        int v = (t >= off) ? sh[t - off] : 0;
        __syncthreads();
        sh[t] += v;
        __syncthreads();
    }
    int incl = sh[t];
    int agg = sh[SCAN_B - 1];
    if (t == 0) {
        if (b == 0) {
            s_base = 0;
            atomicExch(&g_pstate[0], (2ull << 32) | (unsigned)agg);
        } else {
            atomicExch(&g_pstate[b], (1ull << 32) | (unsigned)agg);
        }
    }
    if (b > 0 && t < 32) {
        int running = 0;
        int j = b - 1;
        for (;;) {
            int jj = j - t;
            unsigned long long st;
            unsigned f;
            do {
                st = (jj >= 0) ? ldv64(&g_pstate[jj]) : (2ull << 32);
                f = (unsigned)(st >> 32);
            } while (__ballot_sync(0xffffffffu, f == 0));
            int v = (jj >= 0) ? (int)(st & 0xffffffffu) : 0;
            unsigned pm = __ballot_sync(0xffffffffu, (jj >= 0) && (f == 2));
            if (pm) {
                int fl = __ffs(pm) - 1;
                if ((int)t > fl) v = 0;
#pragma unroll
                for (int o = 16; o; o >>= 1) v += __shfl_xor_sync(0xffffffffu, v, o);
                running += v;
                break;
            }
#pragma unroll
            for (int o = 16; o; o >>= 1) v += __shfl_xor_sync(0xffffffffu, v, o);
            running += v;
            j -= 32;
        }
        if (t == 0) {
            s_base = running;
            atomicExch(&g_pstate[b], (2ull << 32) | (unsigned)(running + agg));
        }
    }
    __syncthreads();
    int base = s_base;
    if (i < NNODES) {
        int r = base + incl - d;
        g_rowptr[i] = r;
        g_cursor[i] = r;
        g_dinv[i] = rsqrtf((float)(d > 0 ? d : 1));
        if (i == NNODES - 1) g_rowptr[NNODES] = base + incl;
    }
}

__global__ void k_fill(const void* __restrict__ eptr) {
    int e4 = (blockIdx.x * blockDim.x + threadIdx.x) * 4;
    if (e4 >= NEDGES) return;
    int s0, s1, s2, s3, d0, d1, d2, d3;
    if (g_flag == 0) {
        const long long* pb = (const long long*)eptr;
        const longlong2* ps = (const longlong2*)(pb + e4);
        const longlong2* pd = (const longlong2*)(pb + NEDGES + e4);
        longlong2 sa = ps[0], sb2 = ps[1], da = pd[0], db = pd[1];
        s0 = (int)sa.x; s1 = (int)sa.y; s2 = (int)sb2.x; s3 = (int)sb2.y;
        d0 = (int)da.x; d1 = (int)da.y; d2 = (int)db.x; d3 = (int)db.y;
    } else {
        const int* pb = (const int*)eptr;
        int4 sa = *(const int4*)(pb + e4);
        int4 da = *(const int4*)(pb + NEDGES + e4);
        s0 = sa.x; s1 = sa.y; s2 = sa.z; s3 = sa.w;
        d0 = da.x; d1 = da.y; d2 = da.z; d3 = da.w;
    }
    int p0 = atomicAdd(&g_cursor[d0], 1);
    int p1 = atomicAdd(&g_cursor[d1], 1);
    int p2 = atomicAdd(&g_cursor[d2], 1);
    int p3 = atomicAdd(&g_cursor[d3], 1);
    g_csrc[p0] = s0;
    g_csrc[p1] = s1;
    g_csrc[p2] = s2;
    g_csrc[p3] = s3;
}
// fold thetas: t0=[3,-3,0.75], t1=[0,3,-1.5], t2=[0,0,0.75]
__global__ void k_fold(const float* __restrict__ Wm1) {
    int idx = blockIdx.x * blockDim.x + threadIdx.x;
    if (idx >= 3 * 64 * 64) return;
    int k = idx >> 12, ij = idx & 4095;
    float c0, c1, c2;
    if (k == 0)      { c0 = 3.0f;  c1 = 0.0f;  c2 = 0.0f;  }
    else if (k == 1) { c0 = -3.0f; c1 = 3.0f;  c2 = 0.0f;  }
    else             { c0 = 0.75f; c1 = -1.5f; c2 = 0.75f; }
    g_wfold[idx] = c0 * Wm1[ij] + c1 * Wm1[4096 + ij] + c2 * Wm1[2 * 4096 + ij];
}
// f0s = f0 * dinv (rowwise), fp16
__global__ void k_scale(const float* __restrict__ f, __half* __restrict__ fs) {
    int idx = blockIdx.x * blockDim.x + threadIdx.x;
    int row = idx >> 5;
    int c2 = idx & 31;
    float dn = g_dinv[row];
    float2 v = *(const float2*)&f[(size_t)row * 64 + c2 * 2];
    *(uint32_t*)&fs[(size_t)row * 64 + c2 * 2] = pack2h(v.x * dn, v.y * dn);
}

// ---------------- smem layout for MMA kernels ----------------
#define LDH 72
#define LDF 68
#define OFF_BIAS 0
#define OFF_WM2  256
#define OFF_CT   768
#define OFF_AH   768
#define OFF_AL   (OFF_AH + 128 * LDH * 2)
#define OFF_WH   (OFF_AL + 128 * LDH * 2)
#define SMEM_SZ  (OFF_WH + 64 * LDH * 2)        // 46848

#define MMA_LOOP(accv)                                                           \
    _Pragma("unroll")                                                            \
    for (int kc = 0; kc < 64; kc += 16) {                                        \
        uint32_t ah[2][4], al[2][4];                                             \
        _Pragma("unroll")                                                        \
        for (int mi = 0; mi < 2; mi++) {                                         \
            uint32_t aa = sb + OFF_AH + ((arow + mi * 16) * LDH + kc + acol) * 2;\
            LDSM4(ah[mi], aa);                                                   \
            LDSM4(al[mi], aa + (OFF_AL - OFF_AH));                               \
        }                                                                        \
        _Pragma("unroll")                                                        \
        for (int ni = 0; ni < 4; ni++) {                                         \
            uint32_t wh[2];                                                      \
            uint32_t ba = sb + OFF_WH + ((brow + ni * 8) * LDH + kc + bcol) * 2; \
            LDSM2(wh, ba);                                                       \
            _Pragma("unroll")                                                    \
            for (int mi = 0; mi < 2; mi++) {                                     \
                MMA(accv[mi][ni], ah[mi], wh);                                   \
                MMA(accv[mi][ni], al[mi], wh);                                   \
            }                                                                    \
        }                                                                        \
    }

#define STAGE_A(pa, lda)                                                         \
    _Pragma("unroll")                                                            \
    for (int it = 0; it < 4; it++) {                                             \
        int idx = tid + it * 256;                                                \
        int row = idx >> 3;                                                      \
        int c8 = (idx & 7) * 8;                                                  \
        int grow = row0 + row;                                                   \
        if (grow >= NNODES) grow = NNODES - 1;                                   \
        const float* gp = (pa) + (size_t)grow * (lda) + c8;                      \
        float4 u0 = *(const float4*)gp;                                          \
        float4 u1 = *(const float4*)(gp + 4);                                    \
        float fv[8] = {u0.x, u0.y, u0.z, u0.w, u1.x, u1.y, u1.z, u1.w};          \
        float lo[8];                                                             \
        _Pragma("unroll")                                                        \
        for (int j = 0; j < 8; j++) {                                            \
            __half h = __float2half_rn(fv[j]);                                   \
            lo[j] = fv[j] - __half2float(h);                                     \
        }                                                                        \
        uint4 vh, vl;                                                            \
        vh.x = pack2h(fv[0], fv[1]); vh.y = pack2h(fv[2], fv[3]);                \
        vh.z = pack2h(fv[4], fv[5]); vh.w = pack2h(fv[6], fv[7]);                \
        vl.x = pack2h(lo[0], lo[1]); vl.y = pack2h(lo[2], lo[3]);                \
        vl.z = pack2h(lo[4], lo[5]); vl.w = pack2h(lo[6], lo[7]);                \
        *(uint4*)&sAh[row * LDH + c8] = vh;                                      \
        *(uint4*)&sAl[row * LDH + c8] = vl;                                      \
    }

#define STAGE_W(Wc)                                                              \
    for (int i = tid; i < 4096; i += 256) {                                      \
        int k = i >> 6, n = i & 63;                                              \
        sWh[n * LDH + k] = __float2half_rn((Wc)[i]);                             \
    }

// ---------------- fused 2-layer MLP: f0 = relu(relu(x@W1+b1)@W2+b2) ----------------
__global__ void __launch_bounds__(256) k_mlp(
    const float* __restrict__ x,
    const float* __restrict__ W1, const float* __restrict__ b1,
    const float* __restrict__ W2, const float* __restrict__ b2,
    float* __restrict__ f0)
{
    extern __shared__ char smem[];
    uint32_t sb = smem_u32(smem);
    float* sbias = (float*)(smem + OFF_BIAS);   // [0..63]=b1, [64..127]=b2
    __half* sAh = (__half*)(smem + OFF_AH);
    __half* sAl = (__half*)(smem + OFF_AL);
    __half* sWh = (__half*)(smem + OFF_WH);

    int tid = threadIdx.x;
    int warp = tid >> 5, lane = tid & 31;
    int wy = warp & 3, wx = warp >> 2;
    int row0 = blockIdx.x * 128;

    if (tid < 64) sbias[tid] = b1[tid];
    else if (tid < 128) sbias[tid] = b2[tid - 64];

    float acc[2][4][4];
#pragma unroll
    for (int mi = 0; mi < 2; mi++)
#pragma unroll
        for (int ni = 0; ni < 4; ni++)
#pragma unroll
            for (int j = 0; j < 4; j++) acc[mi][ni][j] = 0.f;

    const int arow = wy * 32 + (lane & 7) + ((lane >> 3) & 1) * 8;
    const int acol = ((lane >> 4) & 1) * 8;
    const int brow = wx * 32 + (lane & 7);
    const int bcol = ((lane >> 3) & 1) * 8;

    // ---- layer 1 (K=128: two segments of x) ----
    const float* Aseg[2] = {x, x + 64};
#pragma unroll
    for (int sg = 0; sg < 2; sg++) {
        __syncthreads();
        STAGE_A(Aseg[sg], 128);
        STAGE_W(W1 + sg * 4096);
        __syncthreads();
        MMA_LOOP(acc);
    }

    __syncthreads();   // all ldmatrix reads of staged A/W complete
    // ---- convert h1 fragments -> sAh/sAl (A for layer 2), reset acc ----
    {
        int gq = lane >> 2, qp = (lane & 3) * 2;
#pragma unroll
        for (int mi = 0; mi < 2; mi++)
#pragma unroll
            for (int ni = 0; ni < 4; ni++) {
                int r = wy * 32 + mi * 16 + gq;
                int c = wx * 32 + ni * 8 + qp;
                float v00 = fmaxf(acc[mi][ni][0] + sbias[c], 0.f);
                float v01 = fmaxf(acc[mi][ni][1] + sbias[c + 1], 0.f);
                float v10 = fmaxf(acc[mi][ni][2] + sbias[c], 0.f);
                float v11 = fmaxf(acc[mi][ni][3] + sbias[c + 1], 0.f);
                __half h;
                h = __float2half_rn(v00);
                sAh[r * LDH + c] = h;           sAl[r * LDH + c] = __float2half_rn(v00 - __half2float(h));
                h = __float2half_rn(v01);
                sAh[r * LDH + c + 1] = h;       sAl[r * LDH + c + 1] = __float2half_rn(v01 - __half2float(h));
                h = __float2half_rn(v10);
                sAh[(r + 8) * LDH + c] = h;     sAl[(r + 8) * LDH + c] = __float2half_rn(v10 - __half2float(h));
                h = __float2half_rn(v11);
                sAh[(r + 8) * LDH + c + 1] = h; sAl[(r + 8) * LDH + c + 1] = __float2half_rn(v11 - __half2float(h));
                acc[mi][ni][0] = 0.f; acc[mi][ni][1] = 0.f;
                acc[mi][ni][2] = 0.f; acc[mi][ni][3] = 0.f;
            }
    }
    STAGE_W(W2);
    __syncthreads();

    // ---- layer 2 ----
    MMA_LOOP(acc);

    // ---- epilogue: park acc (overlaps dead A staging), add b2 + relu, write f0 ----
    __syncthreads();
    float* sC = (float*)(smem + OFF_CT);
    {
        int gq = lane >> 2, qp = (lane & 3) * 2;
#pragma unroll
        for (int mi = 0; mi < 2; mi++)
#pragma unroll
            for (int ni = 0; ni < 4; ni++) {
                int r = wy * 32 + mi * 16 + gq;
                int c = wx * 32 + ni * 8 + qp;
                *(float2*)&sC[r * LDF + c]       = make_float2(acc[mi][ni][0], acc[mi][ni][1]);
                *(float2*)&sC[(r + 8) * LDF + c] = make_float2(acc[mi][ni][2], acc[mi][ni][3]);
            }
    }
    __syncthreads();
#pragma unroll
    for (int it = 0; it < 4; it++) {
        int idx = tid + it * 256;
        int row = idx >> 3;
        int c8 = (idx & 7) * 8;
        float v[8];
#pragma unroll
        for (int j = 0; j < 8; j++)
            v[j] = fmaxf(sC[row * LDF + c8 + j] + sbias[64 + c8 + j], 0.f);
        size_t base = (size_t)(row0 + row) * 64 + c8;
        *(float4*)(f0 + base)     = make_float4(v[0], v[1], v[2], v[3]);
        *(float4*)(f0 + base + 4) = make_float4(v[4], v[5], v[6], v[7]);
    }
}

// ---------------- head: out = relu(f0@Wf0 + f1@Wf1 + f2@Wf2 + bm1) @ Wm2 + bm2 ----------------
__global__ void __launch_bounds__(256) k_head(
    const float* __restrict__ A0, const float* __restrict__ A1, const float* __restrict__ A2,
    const float* __restrict__ W, const float* __restrict__ bias,
    const float* __restrict__ Wm2, const float* __restrict__ bm2,
    float* __restrict__ out)
{
    extern __shared__ char smem[];
    uint32_t sb = smem_u32(smem);
    float* sbias = (float*)(smem + OFF_BIAS);
    float* swm2  = (float*)(smem + OFF_WM2);
    __half* sAh = (__half*)(smem + OFF_AH);
    __half* sAl = (__half*)(smem + OFF_AL);
    __half* sWh = (__half*)(smem + OFF_WH);

    int tid = threadIdx.x;
    int warp = tid >> 5, lane = tid & 31;
    int wy = warp & 3, wx = warp >> 2;
    int row0 = blockIdx.x * 128;

    if (tid < 64) sbias[tid] = bias[tid];
    if (tid < 128) swm2[tid] = Wm2[tid];

    float acc[2][4][4];
#pragma unroll
    for (int mi = 0; mi < 2; mi++)
#pragma unroll
        for (int ni = 0; ni < 4; ni++)
#pragma unroll
            for (int j = 0; j < 4; j++) acc[mi][ni][j] = 0.f;

    const float* Aseg[3] = {A0, A1, A2};
    const int arow = wy * 32 + (lane & 7) + ((lane >> 3) & 1) * 8;
    const int acol = ((lane >> 4) & 1) * 8;
    const int brow = wx * 32 + (lane & 7);
    const int bcol = ((lane >> 3) & 1) * 8;

#pragma unroll
    for (int sg = 0; sg < 3; sg++) {
        __syncthreads();
        STAGE_A(Aseg[sg], 64);
        STAGE_W(W + sg * 4096);
        __syncthreads();
        MMA_LOOP(acc);
    }

    __syncthreads();
    float* sC = (float*)(smem + OFF_CT);
    {
        int gq = lane >> 2, qp = (lane & 3) * 2;
#pragma unroll
        for (int mi = 0; mi < 2; mi++)
#pragma unroll
            for (int ni = 0; ni < 4; ni++) {
                int r = wy * 32 + mi * 16 + gq;
                int c = wx * 32 + ni * 8 + qp;
                *(float2*)&sC[r * LDF + c]       = make_float2(acc[mi][ni][0], acc[mi][ni][1]);
                *(float2*)&sC[(r + 8) * LDF + c] = make_float2(acc[mi][ni][2], acc[mi][ni][3]);
            }
    }
    __syncthreads();
    int r = tid >> 1, c2 = tid & 1;
    float s = 0.f;
#pragma unroll
    for (int c = 0; c < 64; c++)
        s = fmaf(fmaxf(sC[r * LDF + c] + sbias[c], 0.f), swm2[c * 2 + c2], s);
    if (row0 + r < NNODES)
        out[(size_t)(row0 + r) * 2 + c2] = s + __ldg(&bm2[c2]);
}

// ---------------- propagation (R7-proven: fp16 gather, MLP=4) ----------------
template <bool OUT_SCALED>
__global__ void __launch_bounds__(256) k_prop(
    const float* __restrict__ fin, const __half* __restrict__ fins,
    float* __restrict__ fout, __half* __restrict__ fouts)
{
    int n = (blockIdx.x * blockDim.x + threadIdx.x) >> 5;
    int lane = threadIdx.x & 31;
    int start = g_rowptr[n];
    int end = g_rowptr[n + 1];

    float ax = 0.f, ay = 0.f;
    for (int i = start; i < end; i += 32) {
        int cnt = min(32, end - i);
        int s = 0;
        if (lane < cnt) s = g_csrc[i + lane];
        int j = 0;
        for (; j + 4 <= cnt; j += 4) {
            int s0 = __shfl_sync(0xffffffffu, s, j);
            int s1 = __shfl_sync(0xffffffffu, s, j + 1);
            int s2 = __shfl_sync(0xffffffffu, s, j + 2);
            int s3 = __shfl_sync(0xffffffffu, s, j + 3);
            float2 v0 = __half22float2(*(const __half2*)&fins[(size_t)s0 * 64 + lane * 2]);
            float2 v1 = __half22float2(*(const __half2*)&fins[(size_t)s1 * 64 + lane * 2]);
            float2 v2 = __half22float2(*(const __half2*)&fins[(size_t)s2 * 64 + lane * 2]);
            float2 v3 = __half22float2(*(const __half2*)&fins[(size_t)s3 * 64 + lane * 2]);
            ax += (v0.x + v1.x) + (v2.x + v3.x);
            ay += (v0.y + v1.y) + (v2.y + v3.y);
        }
        for (; j < cnt; j++) {
            int sj = __shfl_sync(0xffffffffu, s, j);
            float2 v = __half22float2(*(const __half2*)&fins[(size_t)sj * 64 + lane * 2]);
            ax += v.x;
            ay += v.y;
        }
    }
    float dn = g_dinv[n];
    size_t base = (size_t)n * 64 + lane * 2;
    float2 cur = *(const float2*)&fin[base];
    float ox = cur.x - ax * dn;
    float oy = cur.y - ay * dn;
    *(float2*)&fout[base] = make_float2(ox, oy);
    if (OUT_SCALED)
        *(uint32_t*)&fouts[base] = pack2h(ox * dn, oy * dn);
}

// ---------------- launch ----------------
extern "C" void kernel_launch(void* const* d_in, const int* in_sizes, int n_in,
                              void* d_out, int out_size)
{
    const float* x   = (const float*)d_in[0];
    const void*  ei  = d_in[1];
    const float* W1  = (const float*)d_in[2];
    const float* b1  = (const float*)d_in[3];
    const float* W2  = (const float*)d_in[4];
    const float* b2  = (const float*)d_in[5];
    const float* Wm1 = (const float*)d_in[6];
    const float* bm1 = (const float*)d_in[7];
    const float* Wm2 = (const float*)d_in[8];
    const float* bm2 = (const float*)d_in[9];
    float* out = (float*)d_out;

    float *f0, *f1, *f2, *pwf;
    __half *f0s, *f1s;
    int *pdeg, *pflag;
    unsigned long long* pstate;
    cudaGetSymbolAddress((void**)&f0, g_f0);
    cudaGetSymbolAddress((void**)&f1, g_f1);
    cudaGetSymbolAddress((void**)&f2, g_f2);
    cudaGetSymbolAddress((void**)&f0s, g_f0s);
    cudaGetSymbolAddress((void**)&f1s, g_f1s);
    cudaGetSymbolAddress((void**)&pwf, g_wfold);
    cudaGetSymbolAddress((void**)&pdeg, g_deg);
    cudaGetSymbolAddress((void**)&pflag, g_flag);
    cudaGetSymbolAddress((void**)&pstate, g_pstate);

    cudaFuncSetAttribute(k_mlp, cudaFuncAttributeMaxDynamicSharedMemorySize, SMEM_SZ);
    cudaFuncSetAttribute(k_head, cudaFuncAttributeMaxDynamicSharedMemorySize, SMEM_SZ);

    static cudaStream_t s_side = [] {
        cudaStream_t s;
        return (cudaStreamCreateWithFlags(&s, cudaStreamNonBlocking) == cudaSuccess)
                   ? s : (cudaStream_t)nullptr;
    }();
    static cudaEvent_t e_fork = [] {
        cudaEvent_t e;
        return (cudaEventCreateWithFlags(&e, cudaEventDisableTiming) == cudaSuccess)
                   ? e : (cudaEvent_t)nullptr;
    }();
    static cudaEvent_t e_dinv = [] {
        cudaEvent_t e;
        return (cudaEventCreateWithFlags(&e, cudaEventDisableTiming) == cudaSuccess)
                   ? e : (cudaEvent_t)nullptr;
    }();
    static cudaEvent_t e_join = [] {
        cudaEvent_t e;
        return (cudaEventCreateWithFlags(&e, cudaEventDisableTiming) == cudaSuccess)
                   ? e : (cudaEvent_t)nullptr;
    }();

    bool overlap = s_side && e_fork && e_dinv && e_join;
    cudaStream_t sp = overlap ? s_side : (cudaStream_t)0;

    if (overlap) {
        cudaEventRecord(e_fork, 0);
        cudaStreamWaitEvent(s_side, e_fork, 0);
    }

    // ---- side chain: fold first, then CSR build ----
    k_fold<<<(3 * 64 * 64 + 255) / 256, 256, 0, sp>>>(Wm1);
    cudaMemsetAsync(pdeg, 0, NNODES * sizeof(int), sp);
    cudaMemsetAsync(pflag, 0, sizeof(int), sp);
    cudaMemsetAsync(pstate, 0, NBLK * sizeof(unsigned long long), sp);
    k_detect<<<1, 256, 0, sp>>>((const int*)ei);
    k_degree<<<EBLK4, 256, 0, sp>>>(ei);
    k_scan_fused<<<NBLK, SCAN_B, 0, sp>>>();
    if (overlap) cudaEventRecord(e_dinv, s_side);
    k_fill<<<EBLK4, 256, 0, sp>>>(ei);
    if (overlap) cudaEventRecord(e_join, s_side);

    // ---- main chain ----
    k_mlp<<<NTILES, 256, SMEM_SZ>>>(x, W1, b1, W2, b2, f0);
    if (overlap) cudaStreamWaitEvent(0, e_dinv, 0);   // prescale needs dinv
    k_scale<<<(NNODES * 32) / 256, 256>>>(f0, f0s);
    if (overlap) cudaStreamWaitEvent(0, e_join, 0);   // props need CSR

    // f1 = P f0, f2 = P f1
    k_prop<true><<<(NNODES * 32) / 256, 256>>>(f0, f0s, f1, f1s);
    k_prop<false><<<(NNODES * 32) / 256, 256>>>(f1, f1s, f2, nullptr);

    // head: out = relu(f0@Wf0 + f1@Wf1 + f2@Wf2 + bm1) @ Wm2 + bm2
    k_head<<<NTILES, 256, SMEM_SZ>>>(f0, f1, f2, pwf, bm1, Wm2, bm2, out);
}